// round 2
// baseline (speedup 1.0000x reference)
#include <cuda_runtime.h>
#include <math.h>

#define DD   128        // embedding dim
#define HH   256        // hyper hidden
#define EMAX 500000
#define SLOTMAX 250000
#define UT   32         // slots per k_u tile

// ---------------- device scratch (static; no allocation) ----------------
__device__ float    g_mid[4];
__device__ float    g_M [DD*DD];
__device__ int      g_counts[EMAX];
__device__ int      g_slot  [EMAX];
__device__ float    g_gsum  [(size_t)SLOTMAX * DD];   // group sums, then u = M^T s (in place)
__device__ float    g_gdenom[SLOTMAX];
__device__ float    g_score [EMAX];
__device__ int      g_medges[EMAX];
__device__ int      g_nslots;
__device__ int      g_nmedges;

// ---------------- kernels ----------------

// zero counts/counters; block 0 additionally runs the hypernetwork
// pref(2) -> h1(256) -> h2(256) -> mid(4)
__global__ void k_zero_hyper(int E,
                             const float* __restrict__ pref,
                             const float* __restrict__ fc1_w, const float* __restrict__ fc1_b,
                             const float* __restrict__ fc2_w, const float* __restrict__ fc2_b,
                             const float* __restrict__ fc3_w, const float* __restrict__ fc3_b) {
    int e = blockIdx.x * blockDim.x + threadIdx.x;
    if (e < E) g_counts[e] = 0;
    if (e == 0) { g_nslots = 0; g_nmedges = 0; }

    if (blockIdx.x == 0) {
        __shared__ float h1[HH];
        __shared__ float h2[HH];
        int t = threadIdx.x;
        float p0 = pref[0], p1 = pref[1];
        h1[t] = p0 * fc1_w[2*t] + p1 * fc1_w[2*t + 1] + fc1_b[t];
        __syncthreads();
        float acc = fc2_b[t];
        #pragma unroll 8
        for (int k = 0; k < HH; k++) acc += h1[k] * fc2_w[t*HH + k];
        h2[t] = acc;
        __syncthreads();
        if (t < 4) {
            float a = fc3_b[t];
            for (int k = 0; k < HH; k++) a += h2[k] * fc3_w[t*HH + k];
            g_mid[t] = a;
        }
    }
}

// M[r,c] = sum_o Wq[o,r] * Wk[o,c], with Wq/Wk synthesized on the fly from mid
__global__ void k_m(const float* __restrict__ wq_w, const float* __restrict__ wk_w) {
    __shared__ float col[DD];               // Wq[:, r]
    int c = threadIdx.x, r = blockIdx.x;
    float m0 = g_mid[0], m1 = g_mid[1], m2 = g_mid[2], m3 = g_mid[3];
    const float2* wq2 = (const float2*)wq_w;
    const float2* wk2 = (const float2*)wk_w;
    float2 q = __ldg(&wq2[c*DD + r]);       // o = c
    col[c] = m0 * q.x + m1 * q.y;
    __syncthreads();
    float acc = 0.f;
    #pragma unroll 16
    for (int o = 0; o < DD; o++) {
        float2 kv = __ldg(&wk2[o*DD + c]);
        acc += col[o] * (m2 * kv.x + m3 * kv.y);
    }
    g_M[r*DD + c] = acc;
}

// count group sizes; the edge observing old==1 claims a compact slot & inits it
__global__ void k_count(const int* __restrict__ seg, int E) {
    int e = blockIdx.x * blockDim.x + threadIdx.x;
    if (e >= E) return;
    int g = seg[e];
    int old = atomicAdd(&g_counts[g], 1);
    if (old == 1) {
        int slot = atomicAdd(&g_nslots, 1);
        g_slot[g]      = slot;
        g_gdenom[slot] = 0.f;
        float4 z = make_float4(0.f, 0.f, 0.f, 0.f);
        float4* row = (float4*)&g_gsum[(size_t)slot * DD];
        #pragma unroll
        for (int i = 0; i < DD/4; i++) row[i] = z;
    }
}

// singleton groups -> prob is exactly 1.0; multi edges compacted into g_medges
__global__ void k_mark(const int* __restrict__ seg, float* __restrict__ out, int E) {
    int e = blockIdx.x * blockDim.x + threadIdx.x;
    if (e >= E) return;
    int g = seg[e];
    if (g_counts[g] == 1) {
        out[e] = 1.0f;
    } else {
        int i = atomicAdd(&g_nmedges, 1);
        g_medges[i] = e;
    }
}

// accumulate edge_emb into group sums (multi edges only); one warp per edge
__global__ void k_accum(const int* __restrict__ seg, const float* __restrict__ emb) {
    int lane = threadIdx.x & 31;
    int w  = (blockIdx.x * blockDim.x + threadIdx.x) >> 5;
    int nw = (gridDim.x * blockDim.x) >> 5;
    int n = g_nmedges;
    for (int i = w; i < n; i += nw) {
        int e = g_medges[i];
        size_t base = (size_t)g_slot[seg[e]] * DD;
        const float* x = emb + (size_t)e * DD;
        #pragma unroll
        for (int j = 0; j < 4; j++)
            atomicAdd(&g_gsum[base + lane + 32*j], x[lane + 32*j]);
    }
}

// u = M^T * sum (in place); 32 slots per block, float4 d-blocking, M via L1
__global__ void __launch_bounds__(DD) k_u() {
    __shared__ float S[UT * DD];            // 16 KB slot tile
    int t = threadIdx.x;
    int ns = g_nslots;
    for (int s0 = blockIdx.x * UT; s0 < ns; s0 += gridDim.x * UT) {
        int nk = min(UT, ns - s0);
        #pragma unroll
        for (int k = 0; k < UT; k++)
            S[k*DD + t] = (k < nk) ? g_gsum[(size_t)(s0 + k) * DD + t] : 0.f;
        __syncthreads();
        float acc[UT];
        #pragma unroll
        for (int k = 0; k < UT; k++) acc[k] = 0.f;
        #pragma unroll 8
        for (int d = 0; d < DD; d += 4) {
            float mv0 = __ldg(&g_M[(d+0)*DD + t]);
            float mv1 = __ldg(&g_M[(d+1)*DD + t]);
            float mv2 = __ldg(&g_M[(d+2)*DD + t]);
            float mv3 = __ldg(&g_M[(d+3)*DD + t]);
            #pragma unroll
            for (int k = 0; k < UT; k++) {
                float4 s4 = *(const float4*)&S[k*DD + d];    // broadcast
                acc[k] += s4.x*mv0 + s4.y*mv1 + s4.z*mv2 + s4.w*mv3;
            }
        }
        __syncthreads();
        for (int k = 0; k < nk; k++)
            g_gsum[(size_t)(s0 + k) * DD + t] = acc[k];
        __syncthreads();
    }
}

// ex_e = exp( 10*tanh( (u_g . x_e)/(c*8*sqrt(128)) - d_e/sqrt(2) ) )
// (no max subtraction: score is clipped to [-10,10], exp is safe in fp32;
//  exp(s)/sum exp(s) == softmax(s - max) exactly in exact arithmetic)
__global__ void k_score(const int* __restrict__ seg, const float* __restrict__ emb,
                        const float* __restrict__ dists, const float* __restrict__ pref) {
    int lane = threadIdx.x & 31;
    int w  = (blockIdx.x * blockDim.x + threadIdx.x) >> 5;
    int nw = (gridDim.x * blockDim.x) >> 5;
    int n = g_nmedges;
    float p0 = pref[0], p1 = pref[1];
    const float inv_scale = 0.011048543456039805f;  // 1/(8*sqrt(128))
    const float inv_sqrt2 = 0.7071067811865476f;
    for (int i = w; i < n; i += nw) {
        int e = g_medges[i];
        int g = seg[e];
        int slot = g_slot[g];
        float c = (float)g_counts[g];
        const float4* u = (const float4*)&g_gsum[(size_t)slot * DD];
        const float4* x = (const float4*)&emb[(size_t)e * DD];
        float4 uv = u[lane];
        float4 xv = x[lane];
        float dot = uv.x*xv.x + uv.y*xv.y + uv.z*xv.z + uv.w*xv.w;
        #pragma unroll
        for (int o = 16; o > 0; o >>= 1) dot += __shfl_xor_sync(0xffffffffu, dot, o);
        if (lane == 0) {
            float de = p0 * dists[2*e] + p1 * dists[2*e + 1];
            float s = dot * inv_scale / c - de * inv_sqrt2;
            float ex = expf(10.0f * tanhf(s));
            g_score[e] = ex;
            atomicAdd(&g_gdenom[slot], ex);
        }
    }
}

__global__ void k_out(const int* __restrict__ seg, float* __restrict__ out) {
    int i0 = blockIdx.x * blockDim.x + threadIdx.x;
    int stride = gridDim.x * blockDim.x;
    int n = g_nmedges;
    for (int i = i0; i < n; i += stride) {
        int e = g_medges[i];
        int slot = g_slot[seg[e]];
        out[e] = g_score[e] / g_gdenom[slot];
    }
}

// ---------------- launch ----------------
extern "C" void kernel_launch(void* const* d_in, const int* in_sizes, int n_in,
                              void* d_out, int out_size) {
    const float* pref     = (const float*)d_in[0];
    const float* dists    = (const float*)d_in[1];
    const float* edge_emb = (const float*)d_in[2];
    const int*   seg      = (const int*)  d_in[3];
    const float* fc1_w    = (const float*)d_in[4];
    const float* fc1_b    = (const float*)d_in[5];
    const float* fc2_w    = (const float*)d_in[6];
    const float* fc2_b    = (const float*)d_in[7];
    const float* fc3_w    = (const float*)d_in[8];
    const float* fc3_b    = (const float*)d_in[9];
    const float* wq_w     = (const float*)d_in[10];
    const float* wk_w     = (const float*)d_in[11];
    float* out = (float*)d_out;

    int E = in_sizes[3];
    int EB = (E + 255) / 256;

    k_zero_hyper<<<EB, 256>>>(E, pref, fc1_w, fc1_b, fc2_w, fc2_b, fc3_w, fc3_b);
    k_m    <<<DD, DD>>>(wq_w, wk_w);
    k_count<<<EB, 256>>>(seg, E);
    k_mark <<<EB, 256>>>(seg, out, E);
    k_accum<<<512, 256>>>(seg, edge_emb);
    k_u    <<<1024, DD>>>();
    k_score<<<1024, 256>>>(seg, edge_emb, dists, pref);
    k_out  <<<256, 256>>>(seg, out);
}

// round 3
// speedup vs baseline: 1.1784x; 1.1784x over previous
#include <cuda_runtime.h>
#include <math.h>

#define DD   128        // embedding dim
#define HH   256        // hyper hidden
#define EMAX 500000
#define SLOTMAX 250000
#define UT   64         // slots per k_u tile

// ---------------- device scratch (static; no allocation) ----------------
__device__ float    g_mid[4];
__device__ float    g_M [DD*DD];
__device__ int      g_counts[EMAX];
__device__ int      g_slot  [EMAX];
__device__ float    g_gsum  [(size_t)SLOTMAX * DD];   // group sums, then u = M^T s (in place)
__device__ float    g_gdenom[SLOTMAX];
__device__ float    g_score [EMAX];
__device__ int      g_medges[EMAX];
__device__ int      g_nslots;
__device__ int      g_nmedges;

// ---------------- helpers ----------------
__device__ __forceinline__ unsigned long long pack2(float s) {
    unsigned long long r;
    asm("mov.b64 %0, {%1, %1};" : "=l"(r) : "r"(__float_as_uint(s)));
    return r;
}
__device__ __forceinline__ void fma2(unsigned long long& d,
                                     unsigned long long a, unsigned long long b) {
    asm("fma.rn.f32x2 %0, %1, %2, %0;" : "+l"(d) : "l"(a), "l"(b));
}
__device__ __forceinline__ void red_add_v4(float* ptr, float4 v) {
    asm volatile("{ .reg .u64 p; cvta.to.global.u64 p, %0;\n\t"
                 "red.global.add.v4.f32 [p], {%1, %2, %3, %4}; }"
                 :: "l"(ptr), "f"(v.x), "f"(v.y), "f"(v.z), "f"(v.w) : "memory");
}

// ---------------- kernels ----------------

// zero counts/counters (vectorized); block 0 additionally runs the hypernetwork
__global__ void k_zero_hyper(int E,
                             const float* __restrict__ pref,
                             const float* __restrict__ fc1_w, const float* __restrict__ fc1_b,
                             const float* __restrict__ fc2_w, const float* __restrict__ fc2_b,
                             const float* __restrict__ fc3_w, const float* __restrict__ fc3_b) {
    int i = blockIdx.x * blockDim.x + threadIdx.x;   // int4 index
    if (i * 4 < E) ((int4*)g_counts)[i] = make_int4(0, 0, 0, 0);
    if (i == 0) { g_nslots = 0; g_nmedges = 0; }

    if (blockIdx.x == 0) {
        __shared__ float h1[HH];
        __shared__ float h2[HH];
        int t = threadIdx.x;
        float p0 = pref[0], p1 = pref[1];
        h1[t] = p0 * fc1_w[2*t] + p1 * fc1_w[2*t + 1] + fc1_b[t];
        __syncthreads();
        float acc = fc2_b[t];
        #pragma unroll 8
        for (int k = 0; k < HH; k++) acc += h1[k] * fc2_w[t*HH + k];
        h2[t] = acc;
        __syncthreads();
        if (t < 4) {
            float a = fc3_b[t];
            for (int k = 0; k < HH; k++) a += h2[k] * fc3_w[t*HH + k];
            g_mid[t] = a;
        }
    }
}

// M[r,c] = sum_o Wq[o,r] * Wk[o,c], Wq/Wk synthesized on the fly from mid
__global__ void k_m(const float* __restrict__ wq_w, const float* __restrict__ wk_w) {
    __shared__ float col[DD];               // Wq[:, r]
    int c = threadIdx.x, r = blockIdx.x;
    float m0 = g_mid[0], m1 = g_mid[1], m2 = g_mid[2], m3 = g_mid[3];
    const float2* wq2 = (const float2*)wq_w;
    const float2* wk2 = (const float2*)wk_w;
    float2 q = __ldg(&wq2[c*DD + r]);       // o = c
    col[c] = m0 * q.x + m1 * q.y;
    __syncthreads();
    float acc = 0.f;
    #pragma unroll 16
    for (int o = 0; o < DD; o++) {
        float2 kv = __ldg(&wk2[o*DD + c]);
        acc += col[o] * (m2 * kv.x + m3 * kv.y);
    }
    g_M[r*DD + c] = acc;
}

// count group sizes (4 edges/thread for MLP); claimers of old==1 get a compact
// slot via warp-aggregated atomics and init it
__global__ void k_count(const int* __restrict__ seg, int E) {
    int base = (blockIdx.x * blockDim.x + threadIdx.x) * 4;
    int lane = threadIdx.x & 31;
    bool valid = base < E;                   // E % 4 == 0
    int4 s4 = make_int4(0, 0, 0, 0);
    int old[4] = {-1, -1, -1, -1};
    if (valid) {
        s4 = *(const int4*)&seg[base];
        old[0] = atomicAdd(&g_counts[s4.x], 1);
        old[1] = atomicAdd(&g_counts[s4.y], 1);
        old[2] = atomicAdd(&g_counts[s4.z], 1);
        old[3] = atomicAdd(&g_counts[s4.w], 1);
    }
    int gs[4] = {s4.x, s4.y, s4.z, s4.w};
    #pragma unroll
    for (int j = 0; j < 4; j++) {
        bool claim = valid && (old[j] == 1);
        unsigned mask = __ballot_sync(0xffffffffu, claim);
        if (mask) {
            int leader = __ffs(mask) - 1;
            int sbase = 0;
            if (lane == leader) sbase = atomicAdd(&g_nslots, __popc(mask));
            sbase = __shfl_sync(0xffffffffu, sbase, leader);
            if (claim) {
                int slot = sbase + __popc(mask & ((1u << lane) - 1u));
                g_slot[gs[j]]  = slot;
                g_gdenom[slot] = 0.f;
                float4 z = make_float4(0.f, 0.f, 0.f, 0.f);
                float4* row = (float4*)&g_gsum[(size_t)slot * DD];
                #pragma unroll
                for (int i = 0; i < DD/4; i++) row[i] = z;
            }
        }
    }
}

// singletons -> prob exactly 1.0; multi edges compacted (warp-aggregated)
__global__ void k_mark(const int* __restrict__ seg, float* __restrict__ out, int E) {
    int base = (blockIdx.x * blockDim.x + threadIdx.x) * 4;
    int lane = threadIdx.x & 31;
    bool valid = base < E;
    int4 s4 = make_int4(0, 0, 0, 0);
    int c[4] = {1, 1, 1, 1};
    if (valid) {
        s4 = *(const int4*)&seg[base];
        c[0] = g_counts[s4.x];
        c[1] = g_counts[s4.y];
        c[2] = g_counts[s4.z];
        c[3] = g_counts[s4.w];
    }
    #pragma unroll
    for (int j = 0; j < 4; j++) {
        bool multi = valid && (c[j] > 1);
        unsigned mask = __ballot_sync(0xffffffffu, multi);
        if (mask) {
            int leader = __ffs(mask) - 1;
            int mbase = 0;
            if (lane == leader) mbase = atomicAdd(&g_nmedges, __popc(mask));
            mbase = __shfl_sync(0xffffffffu, mbase, leader);
            if (multi) g_medges[mbase + __popc(mask & ((1u << lane) - 1u))] = base + j;
        }
        if (valid && !multi) out[base + j] = 1.0f;
    }
}

// accumulate edge_emb into group sums: one warp/edge, vector red (no return)
__global__ void k_accum(const int* __restrict__ seg, const float* __restrict__ emb) {
    int lane = threadIdx.x & 31;
    int w  = (blockIdx.x * blockDim.x + threadIdx.x) >> 5;
    int nw = (gridDim.x * blockDim.x) >> 5;
    int n = g_nmedges;
    for (int i = w; i < n; i += nw) {
        int e = g_medges[i];
        size_t sbase = (size_t)g_slot[seg[e]] * DD;
        float4 x = __ldg(&((const float4*)(emb + (size_t)e * DD))[lane]);
        red_add_v4(&g_gsum[sbase + lane * 4], x);
    }
}

// u = M^T * sum (in place). Register-tiled GEMM: 64 slots x 128 cols per block,
// 128 threads, each 8 slots x 8 cols via packed f32x2 FMA (FFMA2 pipe, 2x fp32).
__global__ void __launch_bounds__(128) k_u() {
    __shared__ float S[UT][DD + 1];          // +1 pad: conflict-free row broadcast
    int t  = threadIdx.x;
    int tx = t & 15;                         // col group: cols [tx*8, tx*8+8)
    int ty = t >> 4;                         // slot group: slots [ty*8, ty*8+8)
    int c0 = tx * 8;
    int ns = g_nslots;
    for (int s0 = blockIdx.x * UT; s0 < ns; s0 += gridDim.x * UT) {
        int nk = min(UT, ns - s0);
        for (int k = 0; k < UT; k++)
            S[k][t] = (k < nk) ? g_gsum[(size_t)(s0 + k) * DD + t] : 0.f;
        __syncthreads();

        unsigned long long acc[8][4];
        #pragma unroll
        for (int i = 0; i < 8; i++)
            #pragma unroll
            for (int j = 0; j < 4; j++) acc[i][j] = 0ull;

        #pragma unroll 2
        for (int d = 0; d < DD; d++) {
            const double2* mrow = (const double2*)&g_M[d*DD + c0];
            double2 ma = __ldg(&mrow[0]);    // cols c0..c0+3 as 2x f32x2
            double2 mb = __ldg(&mrow[1]);    // cols c0+4..c0+7
            unsigned long long m0 = __double_as_longlong(ma.x);
            unsigned long long m1 = __double_as_longlong(ma.y);
            unsigned long long m2 = __double_as_longlong(mb.x);
            unsigned long long m3 = __double_as_longlong(mb.y);
            #pragma unroll
            for (int i = 0; i < 8; i++) {
                unsigned long long s2 = pack2(S[ty*8 + i][d]);
                fma2(acc[i][0], m0, s2);
                fma2(acc[i][1], m1, s2);
                fma2(acc[i][2], m2, s2);
                fma2(acc[i][3], m3, s2);
            }
        }
        __syncthreads();
        #pragma unroll
        for (int i = 0; i < 8; i++) {
            int s = s0 + ty*8 + i;
            if (s < ns) {
                double2* row = (double2*)&g_gsum[(size_t)s * DD + c0];
                row[0] = make_double2(__longlong_as_double(acc[i][0]),
                                      __longlong_as_double(acc[i][1]));
                row[1] = make_double2(__longlong_as_double(acc[i][2]),
                                      __longlong_as_double(acc[i][3]));
            }
        }
        __syncthreads();
    }
}

// ex_e = exp( 10*tanh( (u_g . x_e)/(c*8*sqrt(128)) - d_e/sqrt(2) ) )
// no max subtraction: score clipped to [-10,10] so exp is fp32-safe
__global__ void k_score(const int* __restrict__ seg, const float* __restrict__ emb,
                        const float* __restrict__ dists, const float* __restrict__ pref) {
    int lane = threadIdx.x & 31;
    int w  = (blockIdx.x * blockDim.x + threadIdx.x) >> 5;
    int nw = (gridDim.x * blockDim.x) >> 5;
    int n = g_nmedges;
    float p0 = pref[0], p1 = pref[1];
    const float inv_scale = 0.011048543456039805f;  // 1/(8*sqrt(128))
    const float inv_sqrt2 = 0.7071067811865476f;
    for (int i = w; i < n; i += nw) {
        int e = g_medges[i];
        int g = seg[e];
        int slot = g_slot[g];
        float c = (float)g_counts[g];
        float4 uv = __ldg(&((const float4*)&g_gsum[(size_t)slot * DD])[lane]);
        float4 xv = __ldg(&((const float4*)&emb[(size_t)e * DD])[lane]);
        float dot = uv.x*xv.x + uv.y*xv.y + uv.z*xv.z + uv.w*xv.w;
        #pragma unroll
        for (int o = 16; o > 0; o >>= 1) dot += __shfl_xor_sync(0xffffffffu, dot, o);
        if (lane == 0) {
            float de = p0 * dists[2*e] + p1 * dists[2*e + 1];
            float s = dot * inv_scale / c - de * inv_sqrt2;
            float ex = expf(10.0f * tanhf(s));
            g_score[e] = ex;
            atomicAdd(&g_gdenom[slot], ex);
        }
    }
}

__global__ void k_out(const int* __restrict__ seg, float* __restrict__ out) {
    int i0 = blockIdx.x * blockDim.x + threadIdx.x;
    int stride = gridDim.x * blockDim.x;
    int n = g_nmedges;
    for (int i = i0; i < n; i += stride) {
        int e = g_medges[i];
        int slot = g_slot[seg[e]];
        out[e] = g_score[e] / g_gdenom[slot];
    }
}

// ---------------- launch ----------------
extern "C" void kernel_launch(void* const* d_in, const int* in_sizes, int n_in,
                              void* d_out, int out_size) {
    const float* pref     = (const float*)d_in[0];
    const float* dists    = (const float*)d_in[1];
    const float* edge_emb = (const float*)d_in[2];
    const int*   seg      = (const int*)  d_in[3];
    const float* fc1_w    = (const float*)d_in[4];
    const float* fc1_b    = (const float*)d_in[5];
    const float* fc2_w    = (const float*)d_in[6];
    const float* fc2_b    = (const float*)d_in[7];
    const float* fc3_w    = (const float*)d_in[8];
    const float* fc3_b    = (const float*)d_in[9];
    const float* wq_w     = (const float*)d_in[10];
    const float* wk_w     = (const float*)d_in[11];
    float* out = (float*)d_out;

    int E = in_sizes[3];
    int EB4 = (E/4 + 255) / 256;             // E % 4 == 0 for this problem

    k_zero_hyper<<<EB4, 256>>>(E, pref, fc1_w, fc1_b, fc2_w, fc2_b, fc3_w, fc3_b);
    k_m    <<<DD, DD>>>(wq_w, wk_w);
    k_count<<<EB4, 256>>>(seg, E);
    k_mark <<<EB4, 256>>>(seg, out, E);
    k_accum<<<512, 256>>>(seg, edge_emb);
    k_u    <<<512, 128>>>();
    k_score<<<1024, 256>>>(seg, edge_emb, dists, pref);
    k_out  <<<256, 256>>>(seg, out);
}

// round 4
// speedup vs baseline: 1.1830x; 1.0039x over previous
#include <cuda_runtime.h>
#include <math.h>

#define DD   128        // embedding dim
#define HH   256        // hyper hidden
#define EMAX 500000
#define SLOTMAX 250000
#define UT   64         // slots per k_u tile

// ---------------- device scratch (static; no allocation) ----------------
__device__ float    g_mid[4];
__device__ float    g_M [DD*DD];
__device__ int      g_counts[EMAX];
__device__ int      g_slot  [EMAX];
__device__ float    g_gsum  [(size_t)SLOTMAX * DD];   // group sums, then u = M^T s (in place)
__device__ float    g_gdenom[SLOTMAX];
__device__ float    g_score [EMAX];
__device__ int      g_medges[EMAX];
__device__ int      g_nslots;
__device__ int      g_nmedges;

// ---------------- helpers ----------------
__device__ __forceinline__ unsigned long long pack2(float s) {
    unsigned long long r;
    asm("mov.b64 %0, {%1, %1};" : "=l"(r) : "r"(__float_as_uint(s)));
    return r;
}
__device__ __forceinline__ void fma2(unsigned long long& d,
                                     unsigned long long a, unsigned long long b) {
    asm("fma.rn.f32x2 %0, %1, %2, %0;" : "+l"(d) : "l"(a), "l"(b));
}
__device__ __forceinline__ void red_add_v4(float* ptr, float4 v) {
    asm volatile("{ .reg .u64 p; cvta.to.global.u64 p, %0;\n\t"
                 "red.global.add.v4.f32 [p], {%1, %2, %3, %4}; }"
                 :: "l"(ptr), "f"(v.x), "f"(v.y), "f"(v.z), "f"(v.w) : "memory");
}

// ---------------- kernels ----------------

// zero counts, write out=1.0 for ALL edges (singleton answer; multi edges get
// overwritten by k_out); block 0 additionally runs the hypernetwork.
__global__ void k_zero_hyper(int E, float* __restrict__ out,
                             const float* __restrict__ pref,
                             const float* __restrict__ fc1_w, const float* __restrict__ fc1_b,
                             const float* __restrict__ fc2_w, const float* __restrict__ fc2_b,
                             const float* __restrict__ fc3_w, const float* __restrict__ fc3_b) {
    int i = blockIdx.x * blockDim.x + threadIdx.x;   // quad index (E % 4 == 0)
    if (i * 4 < E) {
        ((int4*)g_counts)[i] = make_int4(0, 0, 0, 0);
        ((float4*)out)[i]    = make_float4(1.f, 1.f, 1.f, 1.f);
    }
    if (i == 0) { g_nslots = 0; g_nmedges = 0; }

    if (blockIdx.x == 0) {
        __shared__ float h1[HH];
        __shared__ float h2[HH];
        int t = threadIdx.x;
        float p0 = pref[0], p1 = pref[1];
        h1[t] = p0 * fc1_w[2*t] + p1 * fc1_w[2*t + 1] + fc1_b[t];
        __syncthreads();
        float acc = fc2_b[t];
        #pragma unroll 8
        for (int k = 0; k < HH; k++) acc += h1[k] * fc2_w[t*HH + k];
        h2[t] = acc;
        __syncthreads();
        if (t < 4) {
            float a = fc3_b[t];
            for (int k = 0; k < HH; k++) a += h2[k] * fc3_w[t*HH + k];
            g_mid[t] = a;
        }
    }
}

// count group sizes (4 edges/thread); the edge observing old==1 claims a
// compact slot (warp-aggregated); claimed rows zeroed warp-cooperatively.
// Blocks 0..63 additionally compute 2 rows each of M = Wq^T Wk (hidden under
// the atomic storm; g_mid was written by the previous launch).
__global__ void k_count_m(const int* __restrict__ seg, int E,
                          const float* __restrict__ wq_w, const float* __restrict__ wk_w) {
    int base = (blockIdx.x * blockDim.x + threadIdx.x) * 4;
    int lane = threadIdx.x & 31;
    bool valid = base < E;                   // E % 4 == 0
    int4 s4 = make_int4(0, 0, 0, 0);
    int old[4] = {-1, -1, -1, -1};
    if (valid) {
        s4 = *(const int4*)&seg[base];
        old[0] = atomicAdd(&g_counts[s4.x], 1);
        old[1] = atomicAdd(&g_counts[s4.y], 1);
        old[2] = atomicAdd(&g_counts[s4.z], 1);
        old[3] = atomicAdd(&g_counts[s4.w], 1);
    }
    int gs[4] = {s4.x, s4.y, s4.z, s4.w};
    float4 z4 = make_float4(0.f, 0.f, 0.f, 0.f);
    #pragma unroll
    for (int j = 0; j < 4; j++) {
        bool claim = valid && (old[j] == 1);
        unsigned cm = __ballot_sync(0xffffffffu, claim);
        if (cm) {
            int leader = __ffs(cm) - 1;
            int sbase = 0;
            if (lane == leader) sbase = atomicAdd(&g_nslots, __popc(cm));
            sbase = __shfl_sync(0xffffffffu, sbase, leader);
            int myslot = sbase + __popc(cm & ((1u << lane) - 1u));
            if (claim) g_slot[gs[j]] = myslot;
            unsigned m = cm;
            while (m) {                      // cooperative row zero per claim
                int src = __ffs(m) - 1; m &= m - 1;
                int slot = __shfl_sync(0xffffffffu, myslot, src);
                ((float4*)&g_gsum[(size_t)slot * DD])[lane] = z4;
                if (lane == 0) g_gdenom[slot] = 0.f;
            }
        }
    }

    // ---- M rows (blocks 0..63, 2 rows per block, all 256 threads) ----
    if (blockIdx.x < DD / 2) {
        __shared__ float col[2][DD];
        int t = threadIdx.x;
        int half = t >> 7;                   // 0 or 1
        int c = t & (DD - 1);
        int r = blockIdx.x * 2 + half;
        float m0 = g_mid[0], m1 = g_mid[1], m2 = g_mid[2], m3 = g_mid[3];
        const float2* wq2 = (const float2*)wq_w;
        const float2* wk2 = (const float2*)wk_w;
        float2 q = __ldg(&wq2[c*DD + r]);    // Wq[c, r]
        col[half][c] = m0 * q.x + m1 * q.y;
        __syncthreads();
        float acc = 0.f;
        #pragma unroll 16
        for (int o = 0; o < DD; o++) {
            float2 kv = __ldg(&wk2[o*DD + c]);
            acc += col[half][o] * (m2 * kv.x + m3 * kv.y);
        }
        g_M[r*DD + c] = acc;
    }
}

// fused mark+accumulate: singletons already have out=1.0 (zero pass).
// Multi edges: compact into g_medges AND cooperatively red-add their
// embedding row into the group sum (whole warp per edge).
__global__ void k_mark_accum(const int* __restrict__ seg,
                             const float* __restrict__ emb, int E) {
    int e = blockIdx.x * blockDim.x + threadIdx.x;
    int lane = threadIdx.x & 31;
    bool valid = e < E;
    int g = 0, c = 1;
    if (valid) { g = seg[e]; c = g_counts[g]; }
    bool multi = valid && (c > 1);
    unsigned mask = __ballot_sync(0xffffffffu, multi);
    if (!mask) return;
    int leader = __ffs(mask) - 1;
    int mbase = 0;
    if (lane == leader) mbase = atomicAdd(&g_nmedges, __popc(mask));
    mbase = __shfl_sync(0xffffffffu, mbase, leader);
    if (multi) g_medges[mbase + __popc(mask & ((1u << lane) - 1u))] = e;

    unsigned m = mask;
    while (m) {
        int src = __ffs(m) - 1; m &= m - 1;
        int eb = __shfl_sync(0xffffffffu, e, src);
        int gb = __shfl_sync(0xffffffffu, g, src);
        int slot = g_slot[gb];               // broadcast load
        float4 x = __ldg(&((const float4*)(emb + (size_t)eb * DD))[lane]);
        red_add_v4(&g_gsum[(size_t)slot * DD + lane * 4], x);
    }
}

// u = M^T * sum (in place). 64 slots x 128 cols per block, 128 threads,
// each 8 slots x 8 cols via packed f32x2 FMA.
__global__ void __launch_bounds__(128) k_u() {
    __shared__ float S[UT][DD + 1];
    int t  = threadIdx.x;
    int tx = t & 15;
    int ty = t >> 4;
    int c0 = tx * 8;
    int ns = g_nslots;
    for (int s0 = blockIdx.x * UT; s0 < ns; s0 += gridDim.x * UT) {
        int nk = min(UT, ns - s0);
        for (int k = 0; k < UT; k++)
            S[k][t] = (k < nk) ? g_gsum[(size_t)(s0 + k) * DD + t] : 0.f;
        __syncthreads();

        unsigned long long acc[8][4];
        #pragma unroll
        for (int i = 0; i < 8; i++)
            #pragma unroll
            for (int j = 0; j < 4; j++) acc[i][j] = 0ull;

        #pragma unroll 2
        for (int d = 0; d < DD; d++) {
            const double2* mrow = (const double2*)&g_M[d*DD + c0];
            double2 ma = __ldg(&mrow[0]);
            double2 mb = __ldg(&mrow[1]);
            unsigned long long m0 = __double_as_longlong(ma.x);
            unsigned long long m1 = __double_as_longlong(ma.y);
            unsigned long long m2 = __double_as_longlong(mb.x);
            unsigned long long m3 = __double_as_longlong(mb.y);
            #pragma unroll
            for (int i = 0; i < 8; i++) {
                unsigned long long s2 = pack2(S[ty*8 + i][d]);
                fma2(acc[i][0], m0, s2);
                fma2(acc[i][1], m1, s2);
                fma2(acc[i][2], m2, s2);
                fma2(acc[i][3], m3, s2);
            }
        }
        __syncthreads();
        #pragma unroll
        for (int i = 0; i < 8; i++) {
            int s = s0 + ty*8 + i;
            if (s < ns) {
                double2* row = (double2*)&g_gsum[(size_t)s * DD + c0];
                row[0] = make_double2(__longlong_as_double(acc[i][0]),
                                      __longlong_as_double(acc[i][1]));
                row[1] = make_double2(__longlong_as_double(acc[i][2]),
                                      __longlong_as_double(acc[i][3]));
            }
        }
        __syncthreads();
    }
}

// ex_e = exp( 10*tanh( (u_g . x_e)/(c*8*sqrt(128)) - d_e/sqrt(2) ) )
// no max subtraction: score clipped to [-10,10] so exp is fp32-safe
__global__ void k_score(const int* __restrict__ seg, const float* __restrict__ emb,
                        const float* __restrict__ dists, const float* __restrict__ pref) {
    int lane = threadIdx.x & 31;
    int w  = (blockIdx.x * blockDim.x + threadIdx.x) >> 5;
    int nw = (gridDim.x * blockDim.x) >> 5;
    int n = g_nmedges;
    float p0 = pref[0], p1 = pref[1];
    const float inv_scale = 0.011048543456039805f;  // 1/(8*sqrt(128))
    const float inv_sqrt2 = 0.7071067811865476f;
    for (int i = w; i < n; i += nw) {
        int e = g_medges[i];
        int g = seg[e];
        int slot = g_slot[g];
        float c = (float)g_counts[g];
        float4 uv = __ldg(&((const float4*)&g_gsum[(size_t)slot * DD])[lane]);
        float4 xv = __ldg(&((const float4*)&emb[(size_t)e * DD])[lane]);
        float dot = uv.x*xv.x + uv.y*xv.y + uv.z*xv.z + uv.w*xv.w;
        #pragma unroll
        for (int o = 16; o > 0; o >>= 1) dot += __shfl_xor_sync(0xffffffffu, dot, o);
        if (lane == 0) {
            float de = p0 * dists[2*e] + p1 * dists[2*e + 1];
            float s = dot * inv_scale / c - de * inv_sqrt2;
            float ex = expf(10.0f * tanhf(s));
            g_score[e] = ex;
            atomicAdd(&g_gdenom[slot], ex);
        }
    }
}

__global__ void k_out(const int* __restrict__ seg, float* __restrict__ out) {
    int i0 = blockIdx.x * blockDim.x + threadIdx.x;
    int stride = gridDim.x * blockDim.x;
    int n = g_nmedges;
    for (int i = i0; i < n; i += stride) {
        int e = g_medges[i];
        int slot = g_slot[seg[e]];
        out[e] = g_score[e] / g_gdenom[slot];
    }
}

// ---------------- launch ----------------
extern "C" void kernel_launch(void* const* d_in, const int* in_sizes, int n_in,
                              void* d_out, int out_size) {
    const float* pref     = (const float*)d_in[0];
    const float* dists    = (const float*)d_in[1];
    const float* edge_emb = (const float*)d_in[2];
    const int*   seg      = (const int*)  d_in[3];
    const float* fc1_w    = (const float*)d_in[4];
    const float* fc1_b    = (const float*)d_in[5];
    const float* fc2_w    = (const float*)d_in[6];
    const float* fc2_b    = (const float*)d_in[7];
    const float* fc3_w    = (const float*)d_in[8];
    const float* fc3_b    = (const float*)d_in[9];
    const float* wq_w     = (const float*)d_in[10];
    const float* wk_w     = (const float*)d_in[11];
    float* out = (float*)d_out;

    int E  = in_sizes[3];
    int EB4 = (E/4 + 255) / 256;             // E % 4 == 0 for this problem
    int EB  = (E + 255) / 256;

    k_zero_hyper <<<EB4, 256>>>(E, out, pref, fc1_w, fc1_b, fc2_w, fc2_b, fc3_w, fc3_b);
    k_count_m    <<<EB4, 256>>>(seg, E, wq_w, wk_w);
    k_mark_accum <<<EB,  256>>>(seg, edge_emb, E);
    k_u          <<<512, 128>>>();
    k_score      <<<1024, 256>>>(seg, edge_emb, dists, pref);
    k_out        <<<512, 256>>>(seg, out);
}

// round 5
// speedup vs baseline: 1.1856x; 1.0022x over previous
#include <cuda_runtime.h>
#include <math.h>

#define DD   128        // embedding dim
#define HH   256        // hyper hidden
#define EMAX 500000
#define SLOTMAX 250000
#define UTS  64         // slots per k_u tile
#define SSTR (DD + 4)   // padded S row stride (keeps 16B align, avoids conflicts)

// ---------------- device scratch (static; no allocation) ----------------
__device__ float    g_mid[4];
__device__ float    g_M [DD*DD];
__device__ int      g_counts[EMAX];
__device__ int      g_slot  [EMAX];
__device__ float    g_gsum  [(size_t)SLOTMAX * DD];   // group sums, then u = M^T s (in place)
__device__ float    g_gdenom[SLOTMAX];
__device__ float    g_score [EMAX];
__device__ int      g_medges[EMAX];
__device__ int      g_nslots;
__device__ int      g_nmedges;

// ---------------- helpers ----------------
__device__ __forceinline__ unsigned long long pack2(float s) {
    unsigned long long r;
    asm("mov.b64 %0, {%1, %1};" : "=l"(r) : "r"(__float_as_uint(s)));
    return r;
}
__device__ __forceinline__ void fma2(unsigned long long& d,
                                     unsigned long long a, unsigned long long b) {
    asm("fma.rn.f32x2 %0, %1, %2, %0;" : "+l"(d) : "l"(a), "l"(b));
}
__device__ __forceinline__ void red_add_v4(float* ptr, float4 v) {
    asm volatile("{ .reg .u64 p; cvta.to.global.u64 p, %0;\n\t"
                 "red.global.add.v4.f32 [p], {%1, %2, %3, %4}; }"
                 :: "l"(ptr), "f"(v.x), "f"(v.y), "f"(v.z), "f"(v.w) : "memory");
}

// ---------------- kernels ----------------

// zero counts, write out=1.0 for ALL edges (singleton answer; multi edges get
// overwritten by k_out); block 0 additionally runs the hypernetwork.
__global__ void k_zero_hyper(int E, float* __restrict__ out,
                             const float* __restrict__ pref,
                             const float* __restrict__ fc1_w, const float* __restrict__ fc1_b,
                             const float* __restrict__ fc2_w, const float* __restrict__ fc2_b,
                             const float* __restrict__ fc3_w, const float* __restrict__ fc3_b) {
    int i = blockIdx.x * blockDim.x + threadIdx.x;   // quad index (E % 4 == 0)
    if (i * 4 < E) {
        ((int4*)g_counts)[i] = make_int4(0, 0, 0, 0);
        ((float4*)out)[i]    = make_float4(1.f, 1.f, 1.f, 1.f);
    }
    if (i == 0) { g_nslots = 0; g_nmedges = 0; }

    if (blockIdx.x == 0) {
        __shared__ float h1[HH];
        __shared__ float h2[HH];
        int t = threadIdx.x;
        float p0 = pref[0], p1 = pref[1];
        h1[t] = p0 * fc1_w[2*t] + p1 * fc1_w[2*t + 1] + fc1_b[t];
        __syncthreads();
        float acc = fc2_b[t];
        #pragma unroll 8
        for (int k = 0; k < HH; k++) acc += h1[k] * fc2_w[t*HH + k];
        h2[t] = acc;
        __syncthreads();
        if (t < 4) {
            float a = fc3_b[t];
            for (int k = 0; k < HH; k++) a += h2[k] * fc3_w[t*HH + k];
            g_mid[t] = a;
        }
    }
}

// count group sizes (4 edges/thread); claimers of old==1 get a compact slot
// (warp-aggregated); claimed rows zeroed warp-cooperatively.
// Blocks 0..63 additionally compute 2 rows each of M = Wq^T Wk (hidden under
// the atomic storm; g_mid was written by the previous launch).
__global__ void k_count_m(const int* __restrict__ seg, int E,
                          const float* __restrict__ wq_w, const float* __restrict__ wk_w) {
    int base = (blockIdx.x * blockDim.x + threadIdx.x) * 4;
    int lane = threadIdx.x & 31;
    bool valid = base < E;                   // E % 4 == 0
    int4 s4 = make_int4(0, 0, 0, 0);
    int old[4] = {-1, -1, -1, -1};
    if (valid) {
        s4 = *(const int4*)&seg[base];
        old[0] = atomicAdd(&g_counts[s4.x], 1);
        old[1] = atomicAdd(&g_counts[s4.y], 1);
        old[2] = atomicAdd(&g_counts[s4.z], 1);
        old[3] = atomicAdd(&g_counts[s4.w], 1);
    }
    int gs[4] = {s4.x, s4.y, s4.z, s4.w};
    float4 z4 = make_float4(0.f, 0.f, 0.f, 0.f);
    #pragma unroll
    for (int j = 0; j < 4; j++) {
        bool claim = valid && (old[j] == 1);
        unsigned cm = __ballot_sync(0xffffffffu, claim);
        if (cm) {
            int leader = __ffs(cm) - 1;
            int sbase = 0;
            if (lane == leader) sbase = atomicAdd(&g_nslots, __popc(cm));
            sbase = __shfl_sync(0xffffffffu, sbase, leader);
            int myslot = sbase + __popc(cm & ((1u << lane) - 1u));
            if (claim) g_slot[gs[j]] = myslot;
            unsigned m = cm;
            while (m) {                      // cooperative row zero per claim
                int src = __ffs(m) - 1; m &= m - 1;
                int slot = __shfl_sync(0xffffffffu, myslot, src);
                ((float4*)&g_gsum[(size_t)slot * DD])[lane] = z4;
                if (lane == 0) g_gdenom[slot] = 0.f;
            }
        }
    }

    // ---- M rows (blocks 0..63, 2 rows per block, all 256 threads) ----
    if (blockIdx.x < DD / 2) {
        __shared__ float col[2][DD];
        int t = threadIdx.x;
        int half = t >> 7;                   // 0 or 1
        int c = t & (DD - 1);
        int r = blockIdx.x * 2 + half;
        float m0 = g_mid[0], m1 = g_mid[1], m2 = g_mid[2], m3 = g_mid[3];
        const float2* wq2 = (const float2*)wq_w;
        const float2* wk2 = (const float2*)wk_w;
        float2 q = __ldg(&wq2[c*DD + r]);    // Wq[c, r]
        col[half][c] = m0 * q.x + m1 * q.y;
        __syncthreads();
        float acc = 0.f;
        #pragma unroll 16
        for (int o = 0; o < DD; o++) {
            float2 kv = __ldg(&wk2[o*DD + c]);
            acc += col[half][o] * (m2 * kv.x + m3 * kv.y);
        }
        g_M[r*DD + c] = acc;
    }
}

// fused mark+accumulate: singletons already have out=1.0 (zero pass).
// Multi edges: compact into g_medges AND cooperatively red-add their
// embedding row into the group sum (whole warp per edge).
__global__ void k_mark_accum(const int* __restrict__ seg,
                             const float* __restrict__ emb, int E) {
    int e = blockIdx.x * blockDim.x + threadIdx.x;
    int lane = threadIdx.x & 31;
    bool valid = e < E;
    int g = 0, c = 1;
    if (valid) { g = seg[e]; c = g_counts[g]; }
    bool multi = valid && (c > 1);
    unsigned mask = __ballot_sync(0xffffffffu, multi);
    if (!mask) return;
    int leader = __ffs(mask) - 1;
    int mbase = 0;
    if (lane == leader) mbase = atomicAdd(&g_nmedges, __popc(mask));
    mbase = __shfl_sync(0xffffffffu, mbase, leader);
    if (multi) g_medges[mbase + __popc(mask & ((1u << lane) - 1u))] = e;

    unsigned m = mask;
    while (m) {
        int src = __ffs(m) - 1; m &= m - 1;
        int eb = __shfl_sync(0xffffffffu, e, src);
        int gb = __shfl_sync(0xffffffffu, g, src);
        int slot = g_slot[gb];               // broadcast load
        float4 x = __ldg(&((const float4*)(emb + (size_t)eb * DD))[lane]);
        red_add_v4(&g_gsum[(size_t)slot * DD + lane * 4], x);
    }
}

// u = M^T * sum (in place). M held ENTIRELY in shared memory (loaded once per
// block, persistent across the tile loop) — no L1 gamble. 64 slots/tile,
// 256 threads, each 4 slots x 8 cols via packed f32x2 FMA.
__global__ void __launch_bounds__(256) k_u() {
    extern __shared__ float sh[];
    float* Msh = sh;                          // DD*DD floats (64 KB)
    float* S   = sh + DD*DD;                  // UTS rows, stride SSTR
    int t = threadIdx.x;
    // load M once per block (coalesced float4)
    for (int i = t; i < DD*DD/4; i += 256)
        ((float4*)Msh)[i] = ((const float4*)g_M)[i];

    int tx = t & 15;                          // col group: cols [tx*8, tx*8+8)
    int ty = t >> 4;                          // slot group: slots [ty*4, ty*4+4)
    int c0 = tx * 8;
    int ns = g_nslots;
    __syncthreads();

    for (int s0 = blockIdx.x * UTS; s0 < ns; s0 += gridDim.x * UTS) {
        int nk = min(UTS, ns - s0);
        // load S tile: UTS x 128 floats as float4 (zero-pad tail rows)
        for (int i = t; i < UTS * (DD/4); i += 256) {
            int r = i >> 5, d4 = i & 31;
            float4 v = (r < nk) ? ((const float4*)&g_gsum[(size_t)(s0 + r) * DD])[d4]
                                : make_float4(0.f, 0.f, 0.f, 0.f);
            *(float4*)&S[r*SSTR + d4*4] = v;
        }
        __syncthreads();

        unsigned long long acc[4][4];
        #pragma unroll
        for (int i = 0; i < 4; i++)
            #pragma unroll
            for (int j = 0; j < 4; j++) acc[i][j] = 0ull;

        #pragma unroll 2
        for (int d = 0; d < DD; d++) {
            const double2* mp = (const double2*)&Msh[d*DD + c0];
            double2 ma = mp[0];               // cols c0..c0+3 as 2x f32x2
            double2 mb = mp[1];               // cols c0+4..c0+7
            unsigned long long m0 = __double_as_longlong(ma.x);
            unsigned long long m1 = __double_as_longlong(ma.y);
            unsigned long long m2 = __double_as_longlong(mb.x);
            unsigned long long m3 = __double_as_longlong(mb.y);
            #pragma unroll
            for (int i = 0; i < 4; i++) {
                unsigned long long s2 = pack2(S[(ty*4 + i)*SSTR + d]);
                fma2(acc[i][0], m0, s2);
                fma2(acc[i][1], m1, s2);
                fma2(acc[i][2], m2, s2);
                fma2(acc[i][3], m3, s2);
            }
        }
        __syncthreads();                      // all S reads done before next fill
        #pragma unroll
        for (int i = 0; i < 4; i++) {
            int s = s0 + ty*4 + i;
            if (s < ns) {
                double2* row = (double2*)&g_gsum[(size_t)s * DD + c0];
                row[0] = make_double2(__longlong_as_double(acc[i][0]),
                                      __longlong_as_double(acc[i][1]));
                row[1] = make_double2(__longlong_as_double(acc[i][2]),
                                      __longlong_as_double(acc[i][3]));
            }
        }
    }
}

// ex_e = exp( 10*tanh( (u_g . x_e)/(c*8*sqrt(128)) - d_e/sqrt(2) ) )
// no max subtraction: score clipped to [-10,10] so exp is fp32-safe
__global__ void k_score(const int* __restrict__ seg, const float* __restrict__ emb,
                        const float* __restrict__ dists, const float* __restrict__ pref) {
    int lane = threadIdx.x & 31;
    int w  = (blockIdx.x * blockDim.x + threadIdx.x) >> 5;
    int nw = (gridDim.x * blockDim.x) >> 5;
    int n = g_nmedges;
    float p0 = pref[0], p1 = pref[1];
    const float inv_scale = 0.011048543456039805f;  // 1/(8*sqrt(128))
    const float inv_sqrt2 = 0.7071067811865476f;
    for (int i = w; i < n; i += nw) {
        int e = g_medges[i];
        int g = seg[e];
        int slot = g_slot[g];
        float c = (float)g_counts[g];
        float4 uv = __ldg(&((const float4*)&g_gsum[(size_t)slot * DD])[lane]);
        float4 xv = __ldg(&((const float4*)&emb[(size_t)e * DD])[lane]);
        float dot = uv.x*xv.x + uv.y*xv.y + uv.z*xv.z + uv.w*xv.w;
        #pragma unroll
        for (int o = 16; o > 0; o >>= 1) dot += __shfl_xor_sync(0xffffffffu, dot, o);
        if (lane == 0) {
            float de = p0 * dists[2*e] + p1 * dists[2*e + 1];
            float s = dot * inv_scale / c - de * inv_sqrt2;
            float ex = expf(10.0f * tanhf(s));
            g_score[e] = ex;
            atomicAdd(&g_gdenom[slot], ex);
        }
    }
}

__global__ void k_out(const int* __restrict__ seg, float* __restrict__ out) {
    int i0 = blockIdx.x * blockDim.x + threadIdx.x;
    int stride = gridDim.x * blockDim.x;
    int n = g_nmedges;
    for (int i = i0; i < n; i += stride) {
        int e = g_medges[i];
        int slot = g_slot[seg[e]];
        out[e] = g_score[e] / g_gdenom[slot];
    }
}

// ---------------- launch ----------------
extern "C" void kernel_launch(void* const* d_in, const int* in_sizes, int n_in,
                              void* d_out, int out_size) {
    const float* pref     = (const float*)d_in[0];
    const float* dists    = (const float*)d_in[1];
    const float* edge_emb = (const float*)d_in[2];
    const int*   seg      = (const int*)  d_in[3];
    const float* fc1_w    = (const float*)d_in[4];
    const float* fc1_b    = (const float*)d_in[5];
    const float* fc2_w    = (const float*)d_in[6];
    const float* fc2_b    = (const float*)d_in[7];
    const float* fc3_w    = (const float*)d_in[8];
    const float* fc3_b    = (const float*)d_in[9];
    const float* wq_w     = (const float*)d_in[10];
    const float* wk_w     = (const float*)d_in[11];
    float* out = (float*)d_out;

    int E  = in_sizes[3];
    int EB4 = (E/4 + 255) / 256;             // E % 4 == 0 for this problem
    int EB  = (E + 255) / 256;

    const int KU_SMEM = (DD*DD + UTS*SSTR) * (int)sizeof(float);  // ~97 KB
    cudaFuncSetAttribute(k_u, cudaFuncAttributeMaxDynamicSharedMemorySize, KU_SMEM);

    k_zero_hyper <<<EB4, 256>>>(E, out, pref, fc1_w, fc1_b, fc2_w, fc2_b, fc3_w, fc3_b);
    k_count_m    <<<EB4, 256>>>(seg, E, wq_w, wk_w);
    k_mark_accum <<<EB,  256>>>(seg, edge_emb, E);
    k_u          <<<304, 256, KU_SMEM>>>();
    k_score      <<<1024, 256>>>(seg, edge_emb, dists, pref);
    k_out        <<<512, 256>>>(seg, out);
}